// round 4
// baseline (speedup 1.0000x reference)
#include <cuda_runtime.h>

#define D 64
#define NMAX 100032
#define EMAX 1600000
#define BM 96

// ---------------- device scratch (no allocations allowed) ----------------
__device__ __align__(16) float g_tmp[NMAX * D];   // activated h (layer>=1)
__device__ __align__(16) float g_u[NMAX * D];     // GEMM1 output (pre inner-BN)
__device__ __align__(16) float g_v[NMAX * D];     // GEMM2 output (pre outer-BN)
__device__ double g_sumA[D], g_sqA[D], g_sumB[D], g_sqB[D];
__device__ int g_deg[NMAX];
__device__ int g_rowptr[NMAX + 1];
__device__ int g_cursor[NMAX];
__device__ int g_csr[EMAX];

// ---------------- CSR build ----------------
__global__ void zero_kernel(int n) {
    int idx = blockIdx.x * blockDim.x + threadIdx.x;
    if (idx < n) g_deg[idx] = 0;
    if (idx < D) { g_sumA[idx] = 0.0; g_sqA[idx] = 0.0; }
}

__global__ void hist_kernel(const int* __restrict__ ei, int E) {
    int e = blockIdx.x * blockDim.x + threadIdx.x;
    if (e < E) atomicAdd(&g_deg[__ldg(&ei[E + e])], 1);
}

__global__ __launch_bounds__(1024) void scan_kernel(int n) {
    __shared__ int s[1024];
    int t = threadIdx.x;
    int chunk = (n + 1023) >> 10;
    int beg = t * chunk;
    int end = min(beg + chunk, n);
    int sum = 0;
    for (int i = beg; i < end; i++) sum += g_deg[i];
    s[t] = sum;
    __syncthreads();
    for (int off = 1; off < 1024; off <<= 1) {
        int x = (t >= off) ? s[t - off] : 0;
        __syncthreads();
        s[t] += x;
        __syncthreads();
    }
    int run = s[t] - sum;   // exclusive prefix
    for (int i = beg; i < end; i++) {
        g_rowptr[i] = run;
        g_cursor[i] = run;
        run += g_deg[i];
    }
    if (t == 1023) g_rowptr[n] = run;
}

__global__ void scatter_kernel(const int* __restrict__ ei, int E) {
    int e = blockIdx.x * blockDim.x + threadIdx.x;
    if (e >= E) return;
    int src = __ldg(&ei[e]);
    int dst = __ldg(&ei[E + e]);
    int pos = atomicAdd(&g_cursor[dst], 1);
    g_csr[pos] = src;
}

// ---------------- per-layer activation: g_tmp = relu(outerBN(v)) ----------------
__global__ void act_kernel(const float* __restrict__ gamma,
                           const float* __restrict__ beta,
                           int n, double inv_n) {
    __shared__ float sc_s[D], sh_s[D];
    int tid = threadIdx.x;
    if (tid < D) {
        double s = g_sumB[tid], q = g_sqB[tid];
        float mean = (float)(s * inv_n);
        float var = (float)(q * inv_n - (s * inv_n) * (s * inv_n));
        float sc = __ldg(&gamma[tid]) * rsqrtf(var + 1e-5f);
        sc_s[tid] = sc;
        sh_s[tid] = __ldg(&beta[tid]) - mean * sc;
        g_sumA[tid] = 0.0;
        g_sqA[tid] = 0.0;
    }
    __syncthreads();
    int idx = blockIdx.x * blockDim.x + tid;
    if (idx >= n * 16) return;
    int q4 = (idx & 15) * 4;
    float4 a = *((const float4*)g_v + idx);
    float4 s = *(const float4*)&sc_s[q4];
    float4 t = *(const float4*)&sh_s[q4];
    float4 o;
    o.x = fmaxf(fmaf(a.x, s.x, t.x), 0.f);
    o.y = fmaxf(fmaf(a.y, s.y, t.y), 0.f);
    o.z = fmaxf(fmaf(a.z, s.z, t.z), 0.f);
    o.w = fmaxf(fmaf(a.w, s.w, t.w), 0.f);
    *((float4*)g_tmp + idx) = o;
}

// ---------------- GEMM1: u = (h + gather_sum(h)) @ W1 + b1; stats -> sumA/sqA ----------------
__global__ __launch_bounds__(256) void gemm1_kernel(
    const float* hsrc,
    const float* __restrict__ Wall, const float* __restrict__ ball,
    int l, int n)
{
    __shared__ float As[BM][68];
    __shared__ float Ws[D][D];
    __shared__ float red[16][D];

    if (!hsrc) hsrc = (const float*)g_tmp;   // layer >= 1

    const float* W = Wall + (size_t)l * D * D;
    const float* bias = ball + (size_t)l * D;
    int tid = threadIdx.x;
    int row0 = blockIdx.x * BM;

    // zero outer-BN accumulators (no readers until gemm2; concurrent 0-stores safe)
    if (tid < D) { g_sumB[tid] = 0.0; g_sqB[tid] = 0.0; }

    #pragma unroll
    for (int i = tid; i < D * D / 4; i += 256)
        ((float4*)Ws)[i] = __ldg((const float4*)W + i);

    // A tile: fused CSR gather-aggregate
    for (int i = tid; i < BM * 16; i += 256) {
        int r = i >> 4, k4 = (i & 15) * 4;
        int gr = row0 + r;
        float4 av = make_float4(0.f, 0.f, 0.f, 0.f);
        if (gr < n) {
            av = __ldg((const float4*)(hsrc + (size_t)gr * D + k4));
            int p = __ldg(&g_rowptr[gr]);
            int pe = __ldg(&g_rowptr[gr + 1]);
            for (; p < pe; p++) {
                int j = __ldg(&g_csr[p]);
                float4 b = __ldg((const float4*)(hsrc + (size_t)j * D + k4));
                av.x += b.x; av.y += b.y; av.z += b.z; av.w += b.w;
            }
        }
        *(float4*)&As[r][k4] = av;
    }
    __syncthreads();

    int tx = tid & 15, ty = tid >> 4;
    int c0 = tx * 4;
    float acc[6][4];
    #pragma unroll
    for (int i = 0; i < 6; i++)
        #pragma unroll
        for (int c = 0; c < 4; c++) acc[i][c] = 0.f;

    #pragma unroll
    for (int k = 0; k < D; k += 4) {
        float4 w0 = *(const float4*)&Ws[k + 0][c0];
        float4 w1 = *(const float4*)&Ws[k + 1][c0];
        float4 w2 = *(const float4*)&Ws[k + 2][c0];
        float4 w3 = *(const float4*)&Ws[k + 3][c0];
        #pragma unroll
        for (int i = 0; i < 6; i++) {
            float4 a = *(const float4*)&As[ty * 6 + i][k];
            acc[i][0] = fmaf(a.x, w0.x, fmaf(a.y, w1.x, fmaf(a.z, w2.x, fmaf(a.w, w3.x, acc[i][0]))));
            acc[i][1] = fmaf(a.x, w0.y, fmaf(a.y, w1.y, fmaf(a.z, w2.y, fmaf(a.w, w3.y, acc[i][1]))));
            acc[i][2] = fmaf(a.x, w0.z, fmaf(a.y, w1.z, fmaf(a.z, w2.z, fmaf(a.w, w3.z, acc[i][2]))));
            acc[i][3] = fmaf(a.x, w0.w, fmaf(a.y, w1.w, fmaf(a.z, w2.w, fmaf(a.w, w3.w, acc[i][3]))));
        }
    }

    float4 bv = *(const float4*)(bias + c0);
    float csum[4] = {0.f, 0.f, 0.f, 0.f};
    float csq[4]  = {0.f, 0.f, 0.f, 0.f};
    #pragma unroll
    for (int i = 0; i < 6; i++) {
        int gr = row0 + ty * 6 + i;
        if (gr < n) {
            float4 o;
            o.x = acc[i][0] + bv.x;
            o.y = acc[i][1] + bv.y;
            o.z = acc[i][2] + bv.z;
            o.w = acc[i][3] + bv.w;
            *(float4*)(g_u + (size_t)gr * D + c0) = o;
            csum[0] += o.x; csq[0] += o.x * o.x;
            csum[1] += o.y; csq[1] += o.y * o.y;
            csum[2] += o.z; csq[2] += o.z * o.z;
            csum[3] += o.w; csq[3] += o.w * o.w;
        }
    }
    __syncthreads();
    #pragma unroll
    for (int c = 0; c < 4; c++) red[ty][c0 + c] = csum[c];
    __syncthreads();
    if (tid < D) {
        float s = 0.f;
        #pragma unroll
        for (int t = 0; t < 16; t++) s += red[t][tid];
        atomicAdd(&g_sumA[tid], (double)s);
    }
    __syncthreads();
    #pragma unroll
    for (int c = 0; c < 4; c++) red[ty][c0 + c] = csq[c];
    __syncthreads();
    if (tid < D) {
        float s = 0.f;
        #pragma unroll
        for (int t = 0; t < 16; t++) s += red[t][tid];
        atomicAdd(&g_sqA[tid], (double)s);
    }
}

// ---------------- GEMM2: v = relu(innerBN(u)) @ W2 + b2; stats -> sumB/sqB ----------------
__global__ __launch_bounds__(256) void gemm2_kernel(
    const float* __restrict__ Wall, const float* __restrict__ ball,
    const float* __restrict__ gamma, const float* __restrict__ beta,
    int l, int n, double inv_n)
{
    __shared__ float As[BM][68];
    __shared__ float Ws[D][D];
    __shared__ float red[16][D];
    __shared__ float sc_s[D], sh_s[D];

    const float* W = Wall + (size_t)l * D * D;
    const float* bias = ball + (size_t)l * D;
    int tid = threadIdx.x;
    int row0 = blockIdx.x * BM;

    if (tid < D) {
        double s = g_sumA[tid], q = g_sqA[tid];
        float mean = (float)(s * inv_n);
        float var = (float)(q * inv_n - (s * inv_n) * (s * inv_n));
        float sc = __ldg(&gamma[tid]) * rsqrtf(var + 1e-5f);
        sc_s[tid] = sc;
        sh_s[tid] = __ldg(&beta[tid]) - mean * sc;
    }

    #pragma unroll
    for (int i = tid; i < D * D / 4; i += 256)
        ((float4*)Ws)[i] = __ldg((const float4*)W + i);
    __syncthreads();

    for (int i = tid; i < BM * 16; i += 256) {
        int r = i >> 4, k4 = (i & 15) * 4;
        int gr = row0 + r;
        float4 av = make_float4(0.f, 0.f, 0.f, 0.f);
        if (gr < n) {
            av = __ldg((const float4*)(g_u + (size_t)gr * D + k4));
            float4 s = *(const float4*)&sc_s[k4];
            float4 t = *(const float4*)&sh_s[k4];
            av.x = fmaxf(fmaf(av.x, s.x, t.x), 0.f);
            av.y = fmaxf(fmaf(av.y, s.y, t.y), 0.f);
            av.z = fmaxf(fmaf(av.z, s.z, t.z), 0.f);
            av.w = fmaxf(fmaf(av.w, s.w, t.w), 0.f);
        }
        *(float4*)&As[r][k4] = av;
    }
    __syncthreads();

    int tx = tid & 15, ty = tid >> 4;
    int c0 = tx * 4;
    float acc[6][4];
    #pragma unroll
    for (int i = 0; i < 6; i++)
        #pragma unroll
        for (int c = 0; c < 4; c++) acc[i][c] = 0.f;

    #pragma unroll
    for (int k = 0; k < D; k += 4) {
        float4 w0 = *(const float4*)&Ws[k + 0][c0];
        float4 w1 = *(const float4*)&Ws[k + 1][c0];
        float4 w2 = *(const float4*)&Ws[k + 2][c0];
        float4 w3 = *(const float4*)&Ws[k + 3][c0];
        #pragma unroll
        for (int i = 0; i < 6; i++) {
            float4 a = *(const float4*)&As[ty * 6 + i][k];
            acc[i][0] = fmaf(a.x, w0.x, fmaf(a.y, w1.x, fmaf(a.z, w2.x, fmaf(a.w, w3.x, acc[i][0]))));
            acc[i][1] = fmaf(a.x, w0.y, fmaf(a.y, w1.y, fmaf(a.z, w2.y, fmaf(a.w, w3.y, acc[i][1]))));
            acc[i][2] = fmaf(a.x, w0.z, fmaf(a.y, w1.z, fmaf(a.z, w2.z, fmaf(a.w, w3.z, acc[i][2]))));
            acc[i][3] = fmaf(a.x, w0.w, fmaf(a.y, w1.w, fmaf(a.z, w2.w, fmaf(a.w, w3.w, acc[i][3]))));
        }
    }

    float4 bv = *(const float4*)(bias + c0);
    float csum[4] = {0.f, 0.f, 0.f, 0.f};
    float csq[4]  = {0.f, 0.f, 0.f, 0.f};
    #pragma unroll
    for (int i = 0; i < 6; i++) {
        int gr = row0 + ty * 6 + i;
        if (gr < n) {
            float4 o;
            o.x = acc[i][0] + bv.x;
            o.y = acc[i][1] + bv.y;
            o.z = acc[i][2] + bv.z;
            o.w = acc[i][3] + bv.w;
            *(float4*)(g_v + (size_t)gr * D + c0) = o;
            csum[0] += o.x; csq[0] += o.x * o.x;
            csum[1] += o.y; csq[1] += o.y * o.y;
            csum[2] += o.z; csq[2] += o.z * o.z;
            csum[3] += o.w; csq[3] += o.w * o.w;
        }
    }
    __syncthreads();
    #pragma unroll
    for (int c = 0; c < 4; c++) red[ty][c0 + c] = csum[c];
    __syncthreads();
    if (tid < D) {
        float s = 0.f;
        #pragma unroll
        for (int t = 0; t < 16; t++) s += red[t][tid];
        atomicAdd(&g_sumB[tid], (double)s);
    }
    __syncthreads();
    #pragma unroll
    for (int c = 0; c < 4; c++) red[ty][c0 + c] = csq[c];
    __syncthreads();
    if (tid < D) {
        float s = 0.f;
        #pragma unroll
        for (int t = 0; t < 16; t++) s += red[t][tid];
        atomicAdd(&g_sqB[tid], (double)s);
    }
}

// ---------------- finalize: outer BN (no relu) -> out[N*D] + gathered out[K*D] ----------------
__global__ void finalize_kernel(const int* __restrict__ bi,
                                const float* __restrict__ gamma,
                                const float* __restrict__ beta,
                                float* __restrict__ out, int n, int K, double inv_n) {
    __shared__ float sc_s[D], sh_s[D];
    int tid = threadIdx.x;
    if (tid < D) {
        double s = g_sumB[tid], q = g_sqB[tid];
        float mean = (float)(s * inv_n);
        float var = (float)(q * inv_n - (s * inv_n) * (s * inv_n));
        float sc = __ldg(&gamma[tid]) * rsqrtf(var + 1e-5f);
        sc_s[tid] = sc;
        sh_s[tid] = __ldg(&beta[tid]) - mean * sc;
    }
    __syncthreads();
    int idx = blockIdx.x * blockDim.x + tid;
    int total = (n + K) * 16;
    if (idx >= total) return;
    int q4 = (idx & 15) * 4;
    int item = idx >> 4;
    int row;
    size_t opos;
    if (item < n) { row = item; opos = (size_t)item * D + q4; }
    else {
        int k = item - n;
        row = __ldg(&bi[k]);
        opos = (size_t)n * D + (size_t)k * D + q4;
    }
    float4 a = *(const float4*)&g_v[(size_t)row * D + q4];
    float4 s = *(const float4*)&sc_s[q4];
    float4 t = *(const float4*)&sh_s[q4];
    float4 o;
    o.x = fmaf(a.x, s.x, t.x);
    o.y = fmaf(a.y, s.y, t.y);
    o.z = fmaf(a.z, s.z, t.z);
    o.w = fmaf(a.w, s.w, t.w);
    *(float4*)&out[opos] = o;
}

extern "C" void kernel_launch(void* const* d_in, const int* in_sizes, int n_in,
                              void* d_out, int out_size) {
    const float* x   = (const float*)d_in[0];
    const int*   ei  = (const int*)d_in[1];
    const int*   bi  = (const int*)d_in[2];
    const float* W1  = (const float*)d_in[3];
    const float* b1  = (const float*)d_in[4];
    const float* g1  = (const float*)d_in[5];
    const float* be1 = (const float*)d_in[6];
    const float* W2  = (const float*)d_in[7];
    const float* b2  = (const float*)d_in[8];
    const float* g2  = (const float*)d_in[9];
    const float* be2 = (const float*)d_in[10];
    float* out = (float*)d_out;

    int n = in_sizes[0] / D;
    int E = in_sizes[1] / 2;
    int K = in_sizes[2];
    int L = in_sizes[3] / (D * D);

    int gN    = (n + 255) / 256;
    int gE    = (E + 255) / 256;
    int gAct  = (n * 16 + 255) / 256;
    int gGemm = (n + BM - 1) / BM;
    int gFin  = ((n + K) * 16 + 255) / 256;
    double inv_n = 1.0 / (double)n;

    zero_kernel<<<gN, 256>>>(n);
    hist_kernel<<<gE, 256>>>(ei, E);
    scan_kernel<<<1, 1024>>>(n);
    scatter_kernel<<<gE, 256>>>(ei, E);

    for (int l = 0; l < L; l++) {
        if (l > 0)
            act_kernel<<<gAct, 256>>>(g2 + (size_t)(l - 1) * D, be2 + (size_t)(l - 1) * D, n, inv_n);
        gemm1_kernel<<<gGemm, 256>>>((l == 0) ? x : nullptr, W1, b1, l, n);
        gemm2_kernel<<<gGemm, 256>>>(W2, b2, g1 + (size_t)l * D, be1 + (size_t)l * D, l, n, inv_n);
    }
    finalize_kernel<<<gFin, 256>>>(bi, g2 + (size_t)(L - 1) * D, be2 + (size_t)(L - 1) * D, out, n, K, inv_n);
}

// round 5
// speedup vs baseline: 1.0495x; 1.0495x over previous
#include <cuda_runtime.h>

#define D 64
#define NMAX 100032
#define EMAX 1600000
#define BM 96

// ---------------- device scratch (no allocations allowed) ----------------
__device__ __align__(16) float g_tmp[NMAX * D];   // activated h (layer>=1)
__device__ __align__(16) float g_u[NMAX * D];     // GEMM1 output (pre inner-BN)
__device__ __align__(16) float g_v[NMAX * D];     // GEMM2 output (pre outer-BN)
__device__ double g_sumA[D], g_sqA[D], g_sumB[D], g_sqB[D];
__device__ int g_deg[NMAX];
__device__ int g_rowptr[NMAX + 1];
__device__ int g_cursor[NMAX];
__device__ int g_csr[EMAX];

// ---------------- CSR build ----------------
__global__ void zero_kernel(int n) {
    int idx = blockIdx.x * blockDim.x + threadIdx.x;
    if (idx < n) g_deg[idx] = 0;
    if (idx < D) { g_sumA[idx] = 0.0; g_sqA[idx] = 0.0; }
}

__global__ void hist_kernel(const int* __restrict__ ei, int E) {
    int e = blockIdx.x * blockDim.x + threadIdx.x;
    if (e < E) atomicAdd(&g_deg[__ldg(&ei[E + e])], 1);
}

__global__ __launch_bounds__(1024) void scan_kernel(int n) {
    __shared__ int s[1024];
    int t = threadIdx.x;
    int chunk = (n + 1023) >> 10;
    int beg = t * chunk;
    int end = min(beg + chunk, n);
    int sum = 0;
    for (int i = beg; i < end; i++) sum += g_deg[i];
    s[t] = sum;
    __syncthreads();
    for (int off = 1; off < 1024; off <<= 1) {
        int x = (t >= off) ? s[t - off] : 0;
        __syncthreads();
        s[t] += x;
        __syncthreads();
    }
    int run = s[t] - sum;   // exclusive prefix
    for (int i = beg; i < end; i++) {
        g_rowptr[i] = run;
        g_cursor[i] = run;
        run += g_deg[i];
    }
    if (t == 1023) g_rowptr[n] = run;
}

__global__ void scatter_kernel(const int* __restrict__ ei, int E) {
    int e = blockIdx.x * blockDim.x + threadIdx.x;
    if (e >= E) return;
    int src = __ldg(&ei[e]);
    int dst = __ldg(&ei[E + e]);
    int pos = atomicAdd(&g_cursor[dst], 1);
    g_csr[pos] = src;
}

// ---------------- per-layer activation: g_tmp = relu(outerBN(v)) ----------------
__global__ void act_kernel(const float* __restrict__ gamma,
                           const float* __restrict__ beta,
                           int n, double inv_n) {
    __shared__ float sc_s[D], sh_s[D];
    int tid = threadIdx.x;
    if (tid < D) {
        double s = g_sumB[tid], q = g_sqB[tid];
        float mean = (float)(s * inv_n);
        float var = (float)(q * inv_n - (s * inv_n) * (s * inv_n));
        float sc = __ldg(&gamma[tid]) * rsqrtf(var + 1e-5f);
        sc_s[tid] = sc;
        sh_s[tid] = __ldg(&beta[tid]) - mean * sc;
        g_sumA[tid] = 0.0;
        g_sqA[tid] = 0.0;
    }
    __syncthreads();
    int idx = blockIdx.x * blockDim.x + tid;
    if (idx >= n * 16) return;
    int q4 = (idx & 15) * 4;
    float4 a = *((const float4*)g_v + idx);
    float4 s = *(const float4*)&sc_s[q4];
    float4 t = *(const float4*)&sh_s[q4];
    float4 o;
    o.x = fmaxf(fmaf(a.x, s.x, t.x), 0.f);
    o.y = fmaxf(fmaf(a.y, s.y, t.y), 0.f);
    o.z = fmaxf(fmaf(a.z, s.z, t.z), 0.f);
    o.w = fmaxf(fmaf(a.w, s.w, t.w), 0.f);
    *((float4*)g_tmp + idx) = o;
}

// ---------------- GEMM1: u = (h + gather_sum(h)) @ W1 + b1; stats -> sumA/sqA ----------------
__global__ __launch_bounds__(256) void gemm1_kernel(
    const float* hsrc,
    const float* __restrict__ Wall, const float* __restrict__ ball,
    int l, int n)
{
    __shared__ float As[BM][68];
    __shared__ float Ws[D][D];
    __shared__ float red[16][D];

    if (!hsrc) hsrc = (const float*)g_tmp;   // layer >= 1

    const float* W = Wall + (size_t)l * D * D;
    const float* bias = ball + (size_t)l * D;
    int tid = threadIdx.x;
    int row0 = blockIdx.x * BM;

    // zero outer-BN accumulators (no readers until gemm2; concurrent 0-stores safe)
    if (tid < D) { g_sumB[tid] = 0.0; g_sqB[tid] = 0.0; }

    #pragma unroll
    for (int i = tid; i < D * D / 4; i += 256)
        ((float4*)Ws)[i] = __ldg((const float4*)W + i);

    // A tile: fused CSR gather-aggregate, unrolled x4 for MLP
    for (int i = tid; i < BM * 16; i += 256) {
        int r = i >> 4, k4 = (i & 15) * 4;
        int gr = row0 + r;
        float4 av = make_float4(0.f, 0.f, 0.f, 0.f);
        if (gr < n) {
            av = __ldg((const float4*)(hsrc + (size_t)gr * D + k4));
            int p  = __ldg(&g_rowptr[gr]);
            int pe = __ldg(&g_rowptr[gr + 1]);
            float4 acc1 = make_float4(0.f, 0.f, 0.f, 0.f);
            float4 acc2 = make_float4(0.f, 0.f, 0.f, 0.f);
            float4 acc3 = make_float4(0.f, 0.f, 0.f, 0.f);
            for (; p + 4 <= pe; p += 4) {
                int j0 = __ldg(&g_csr[p + 0]);
                int j1 = __ldg(&g_csr[p + 1]);
                int j2 = __ldg(&g_csr[p + 2]);
                int j3 = __ldg(&g_csr[p + 3]);
                float4 b0 = __ldg((const float4*)(hsrc + (size_t)j0 * D + k4));
                float4 b1 = __ldg((const float4*)(hsrc + (size_t)j1 * D + k4));
                float4 b2 = __ldg((const float4*)(hsrc + (size_t)j2 * D + k4));
                float4 b3 = __ldg((const float4*)(hsrc + (size_t)j3 * D + k4));
                av.x += b0.x;   av.y += b0.y;   av.z += b0.z;   av.w += b0.w;
                acc1.x += b1.x; acc1.y += b1.y; acc1.z += b1.z; acc1.w += b1.w;
                acc2.x += b2.x; acc2.y += b2.y; acc2.z += b2.z; acc2.w += b2.w;
                acc3.x += b3.x; acc3.y += b3.y; acc3.z += b3.z; acc3.w += b3.w;
            }
            if (p < pe) {
                int j0 = __ldg(&g_csr[p]);
                int j1 = (p + 1 < pe) ? __ldg(&g_csr[p + 1]) : -1;
                int j2 = (p + 2 < pe) ? __ldg(&g_csr[p + 2]) : -1;
                float4 b0 = __ldg((const float4*)(hsrc + (size_t)j0 * D + k4));
                av.x += b0.x; av.y += b0.y; av.z += b0.z; av.w += b0.w;
                if (j1 >= 0) {
                    float4 b1 = __ldg((const float4*)(hsrc + (size_t)j1 * D + k4));
                    acc1.x += b1.x; acc1.y += b1.y; acc1.z += b1.z; acc1.w += b1.w;
                }
                if (j2 >= 0) {
                    float4 b2 = __ldg((const float4*)(hsrc + (size_t)j2 * D + k4));
                    acc2.x += b2.x; acc2.y += b2.y; acc2.z += b2.z; acc2.w += b2.w;
                }
            }
            av.x += acc1.x + acc2.x + acc3.x;
            av.y += acc1.y + acc2.y + acc3.y;
            av.z += acc1.z + acc2.z + acc3.z;
            av.w += acc1.w + acc2.w + acc3.w;
        }
        *(float4*)&As[r][k4] = av;
    }
    __syncthreads();

    int tx = tid & 15, ty = tid >> 4;
    int c0 = tx * 4;
    float acc[6][4];
    #pragma unroll
    for (int i = 0; i < 6; i++)
        #pragma unroll
        for (int c = 0; c < 4; c++) acc[i][c] = 0.f;

    #pragma unroll
    for (int k = 0; k < D; k += 4) {
        float4 w0 = *(const float4*)&Ws[k + 0][c0];
        float4 w1 = *(const float4*)&Ws[k + 1][c0];
        float4 w2 = *(const float4*)&Ws[k + 2][c0];
        float4 w3 = *(const float4*)&Ws[k + 3][c0];
        #pragma unroll
        for (int i = 0; i < 6; i++) {
            float4 a = *(const float4*)&As[ty * 6 + i][k];
            acc[i][0] = fmaf(a.x, w0.x, fmaf(a.y, w1.x, fmaf(a.z, w2.x, fmaf(a.w, w3.x, acc[i][0]))));
            acc[i][1] = fmaf(a.x, w0.y, fmaf(a.y, w1.y, fmaf(a.z, w2.y, fmaf(a.w, w3.y, acc[i][1]))));
            acc[i][2] = fmaf(a.x, w0.z, fmaf(a.y, w1.z, fmaf(a.z, w2.z, fmaf(a.w, w3.z, acc[i][2]))));
            acc[i][3] = fmaf(a.x, w0.w, fmaf(a.y, w1.w, fmaf(a.z, w2.w, fmaf(a.w, w3.w, acc[i][3]))));
        }
    }

    float4 bv = *(const float4*)(bias + c0);
    float csum[4] = {0.f, 0.f, 0.f, 0.f};
    float csq[4]  = {0.f, 0.f, 0.f, 0.f};
    #pragma unroll
    for (int i = 0; i < 6; i++) {
        int gr = row0 + ty * 6 + i;
        if (gr < n) {
            float4 o;
            o.x = acc[i][0] + bv.x;
            o.y = acc[i][1] + bv.y;
            o.z = acc[i][2] + bv.z;
            o.w = acc[i][3] + bv.w;
            *(float4*)(g_u + (size_t)gr * D + c0) = o;
            csum[0] += o.x; csq[0] += o.x * o.x;
            csum[1] += o.y; csq[1] += o.y * o.y;
            csum[2] += o.z; csq[2] += o.z * o.z;
            csum[3] += o.w; csq[3] += o.w * o.w;
        }
    }
    __syncthreads();
    #pragma unroll
    for (int c = 0; c < 4; c++) red[ty][c0 + c] = csum[c];
    __syncthreads();
    if (tid < D) {
        float s = 0.f;
        #pragma unroll
        for (int t = 0; t < 16; t++) s += red[t][tid];
        atomicAdd(&g_sumA[tid], (double)s);
    }
    __syncthreads();
    #pragma unroll
    for (int c = 0; c < 4; c++) red[ty][c0 + c] = csq[c];
    __syncthreads();
    if (tid < D) {
        float s = 0.f;
        #pragma unroll
        for (int t = 0; t < 16; t++) s += red[t][tid];
        atomicAdd(&g_sqA[tid], (double)s);
    }
}

// ---------------- GEMM2: v = relu(innerBN(u)) @ W2 + b2; stats -> sumB/sqB ----------------
__global__ __launch_bounds__(256) void gemm2_kernel(
    const float* __restrict__ Wall, const float* __restrict__ ball,
    const float* __restrict__ gamma, const float* __restrict__ beta,
    int l, int n, double inv_n)
{
    __shared__ float As[BM][68];
    __shared__ float Ws[D][D];
    __shared__ float red[16][D];
    __shared__ float sc_s[D], sh_s[D];

    const float* W = Wall + (size_t)l * D * D;
    const float* bias = ball + (size_t)l * D;
    int tid = threadIdx.x;
    int row0 = blockIdx.x * BM;

    if (tid < D) {
        double s = g_sumA[tid], q = g_sqA[tid];
        float mean = (float)(s * inv_n);
        float var = (float)(q * inv_n - (s * inv_n) * (s * inv_n));
        float sc = __ldg(&gamma[tid]) * rsqrtf(var + 1e-5f);
        sc_s[tid] = sc;
        sh_s[tid] = __ldg(&beta[tid]) - mean * sc;
    }

    #pragma unroll
    for (int i = tid; i < D * D / 4; i += 256)
        ((float4*)Ws)[i] = __ldg((const float4*)W + i);
    __syncthreads();

    for (int i = tid; i < BM * 16; i += 256) {
        int r = i >> 4, k4 = (i & 15) * 4;
        int gr = row0 + r;
        float4 av = make_float4(0.f, 0.f, 0.f, 0.f);
        if (gr < n) {
            av = __ldg((const float4*)(g_u + (size_t)gr * D + k4));
            float4 s = *(const float4*)&sc_s[k4];
            float4 t = *(const float4*)&sh_s[k4];
            av.x = fmaxf(fmaf(av.x, s.x, t.x), 0.f);
            av.y = fmaxf(fmaf(av.y, s.y, t.y), 0.f);
            av.z = fmaxf(fmaf(av.z, s.z, t.z), 0.f);
            av.w = fmaxf(fmaf(av.w, s.w, t.w), 0.f);
        }
        *(float4*)&As[r][k4] = av;
    }
    __syncthreads();

    int tx = tid & 15, ty = tid >> 4;
    int c0 = tx * 4;
    float acc[6][4];
    #pragma unroll
    for (int i = 0; i < 6; i++)
        #pragma unroll
        for (int c = 0; c < 4; c++) acc[i][c] = 0.f;

    #pragma unroll
    for (int k = 0; k < D; k += 4) {
        float4 w0 = *(const float4*)&Ws[k + 0][c0];
        float4 w1 = *(const float4*)&Ws[k + 1][c0];
        float4 w2 = *(const float4*)&Ws[k + 2][c0];
        float4 w3 = *(const float4*)&Ws[k + 3][c0];
        #pragma unroll
        for (int i = 0; i < 6; i++) {
            float4 a = *(const float4*)&As[ty * 6 + i][k];
            acc[i][0] = fmaf(a.x, w0.x, fmaf(a.y, w1.x, fmaf(a.z, w2.x, fmaf(a.w, w3.x, acc[i][0]))));
            acc[i][1] = fmaf(a.x, w0.y, fmaf(a.y, w1.y, fmaf(a.z, w2.y, fmaf(a.w, w3.y, acc[i][1]))));
            acc[i][2] = fmaf(a.x, w0.z, fmaf(a.y, w1.z, fmaf(a.z, w2.z, fmaf(a.w, w3.z, acc[i][2]))));
            acc[i][3] = fmaf(a.x, w0.w, fmaf(a.y, w1.w, fmaf(a.z, w2.w, fmaf(a.w, w3.w, acc[i][3]))));
        }
    }

    float4 bv = *(const float4*)(bias + c0);
    float csum[4] = {0.f, 0.f, 0.f, 0.f};
    float csq[4]  = {0.f, 0.f, 0.f, 0.f};
    #pragma unroll
    for (int i = 0; i < 6; i++) {
        int gr = row0 + ty * 6 + i;
        if (gr < n) {
            float4 o;
            o.x = acc[i][0] + bv.x;
            o.y = acc[i][1] + bv.y;
            o.z = acc[i][2] + bv.z;
            o.w = acc[i][3] + bv.w;
            *(float4*)(g_v + (size_t)gr * D + c0) = o;
            csum[0] += o.x; csq[0] += o.x * o.x;
            csum[1] += o.y; csq[1] += o.y * o.y;
            csum[2] += o.z; csq[2] += o.z * o.z;
            csum[3] += o.w; csq[3] += o.w * o.w;
        }
    }
    __syncthreads();
    #pragma unroll
    for (int c = 0; c < 4; c++) red[ty][c0 + c] = csum[c];
    __syncthreads();
    if (tid < D) {
        float s = 0.f;
        #pragma unroll
        for (int t = 0; t < 16; t++) s += red[t][tid];
        atomicAdd(&g_sumB[tid], (double)s);
    }
    __syncthreads();
    #pragma unroll
    for (int c = 0; c < 4; c++) red[ty][c0 + c] = csq[c];
    __syncthreads();
    if (tid < D) {
        float s = 0.f;
        #pragma unroll
        for (int t = 0; t < 16; t++) s += red[t][tid];
        atomicAdd(&g_sqB[tid], (double)s);
    }
}

// ---------------- finalize: outer BN (no relu) -> out[N*D] + gathered out[K*D] ----------------
__global__ void finalize_kernel(const int* __restrict__ bi,
                                const float* __restrict__ gamma,
                                const float* __restrict__ beta,
                                float* __restrict__ out, int n, int K, double inv_n) {
    __shared__ float sc_s[D], sh_s[D];
    int tid = threadIdx.x;
    if (tid < D) {
        double s = g_sumB[tid], q = g_sqB[tid];
        float mean = (float)(s * inv_n);
        float var = (float)(q * inv_n - (s * inv_n) * (s * inv_n));
        float sc = __ldg(&gamma[tid]) * rsqrtf(var + 1e-5f);
        sc_s[tid] = sc;
        sh_s[tid] = __ldg(&beta[tid]) - mean * sc;
    }
    __syncthreads();
    int idx = blockIdx.x * blockDim.x + tid;
    int total = (n + K) * 16;
    if (idx >= total) return;
    int q4 = (idx & 15) * 4;
    int item = idx >> 4;
    int row;
    size_t opos;
    if (item < n) { row = item; opos = (size_t)item * D + q4; }
    else {
        int k = item - n;
        row = __ldg(&bi[k]);
        opos = (size_t)n * D + (size_t)k * D + q4;
    }
    float4 a = *(const float4*)&g_v[(size_t)row * D + q4];
    float4 s = *(const float4*)&sc_s[q4];
    float4 t = *(const float4*)&sh_s[q4];
    float4 o;
    o.x = fmaf(a.x, s.x, t.x);
    o.y = fmaf(a.y, s.y, t.y);
    o.z = fmaf(a.z, s.z, t.z);
    o.w = fmaf(a.w, s.w, t.w);
    *(float4*)&out[opos] = o;
}

extern "C" void kernel_launch(void* const* d_in, const int* in_sizes, int n_in,
                              void* d_out, int out_size) {
    const float* x   = (const float*)d_in[0];
    const int*   ei  = (const int*)d_in[1];
    const int*   bi  = (const int*)d_in[2];
    const float* W1  = (const float*)d_in[3];
    const float* b1  = (const float*)d_in[4];
    const float* g1  = (const float*)d_in[5];
    const float* be1 = (const float*)d_in[6];
    const float* W2  = (const float*)d_in[7];
    const float* b2  = (const float*)d_in[8];
    const float* g2  = (const float*)d_in[9];
    const float* be2 = (const float*)d_in[10];
    float* out = (float*)d_out;

    int n = in_sizes[0] / D;
    int E = in_sizes[1] / 2;
    int K = in_sizes[2];
    int L = in_sizes[3] / (D * D);

    int gN    = (n + 255) / 256;
    int gE    = (E + 255) / 256;
    int gAct  = (n * 16 + 255) / 256;
    int gGemm = (n + BM - 1) / BM;
    int gFin  = ((n + K) * 16 + 255) / 256;
    double inv_n = 1.0 / (double)n;

    zero_kernel<<<gN, 256>>>(n);
    hist_kernel<<<gE, 256>>>(ei, E);
    scan_kernel<<<1, 1024>>>(n);
    scatter_kernel<<<gE, 256>>>(ei, E);

    for (int l = 0; l < L; l++) {
        if (l > 0)
            act_kernel<<<gAct, 256>>>(g2 + (size_t)(l - 1) * D, be2 + (size_t)(l - 1) * D, n, inv_n);
        gemm1_kernel<<<gGemm, 256>>>((l == 0) ? x : nullptr, W1, b1, l, n);
        gemm2_kernel<<<gGemm, 256>>>(W2, b2, g1 + (size_t)l * D, be1 + (size_t)l * D, l, n, inv_n);
    }
    finalize_kernel<<<gFin, 256>>>(bi, g2 + (size_t)(L - 1) * D, be2 + (size_t)(L - 1) * D, out, n, K, inv_n);
}